// round 12
// baseline (speedup 1.0000x reference)
#include <cuda_runtime.h>
#include <math.h>

#define KU 128      // users (K)
#define MD 1024     // M
#define NU 128      // N (== KU)
#define KT 8        // k rows per block tile
#define MCH 32      // m rows per block chunk
#define NKT (KU / KT)    // 16
#define NMC (MD / MCH)   // 32
static __device__ __constant__ float N0F = 1e-11f;  // 10^(-80/10)/1000

// Scratch (static __device__ — no allocation)
__device__ float d_gp_re[NMC * KU * NU];   // per-m-chunk partials of g (2 MB)
__device__ float d_gp_im[NMC * KU * NU];
__device__ float d_R[KU];
__device__ unsigned int d_ctr;             // last-block counter for k3

// ---------------------------------------------------------------------------
// k12: stage A thread-per-row (NO shfl): thread (kk=warp, m=lane) streams its
// 2x512B row pair sequentially (8 float4 per 128B line -> 1 miss + 7 L1 hits),
// accumulating 4 dot products in registers with v broadcast from smem.
// stage B contracts h tile against W[m0:m0+32,:] (L2) -> g partials.
// grid (32 mc, 16 kt) = 512 blocks x 256 threads.
// ---------------------------------------------------------------------------
__global__ __launch_bounds__(256, 3) void k12_fused(
    const float* __restrict__ Wv,
    const float* __restrict__ Ar,
    const float* __restrict__ Ai,
    const float* __restrict__ hdr,
    const float* __restrict__ hdi)
{
    __shared__ float vs[256];         // v_re | v_im
    __shared__ float hsrt[MCH * 8];   // h_re transposed [m][kk]
    __shared__ float hsit[MCH * 8];   // h_im transposed [m][kk]

    const int tid  = threadIdx.x;
    const int lane = tid & 31;
    const int warp = tid >> 5;        // 0..7 == kk

    const int mc = blockIdx.x;        // 0..31
    const int kt = blockIdx.y;        // 0..15
    const int k0 = kt * KT;
    const int m0 = mc * MCH;

    vs[tid] = Wv[tid];                // 256 floats of v
    __syncthreads();

    // ---- stage A: one row per thread, 4 register-resident dot accumulators ----
    {
        const int kk = warp;
        const int m  = lane;
        const size_t row = (size_t)(k0 + kk) * MD + m0 + m;
        const float4* a4  = reinterpret_cast<const float4*>(Ar + row * NU);
        const float4* b4  = reinterpret_cast<const float4*>(Ai + row * NU);
        const float4* v4r = reinterpret_cast<const float4*>(vs);
        const float4* v4i = reinterpret_cast<const float4*>(vs + 128);

        float rr = 0.f, ri = 0.f, ir = 0.f, ii = 0.f;
#pragma unroll 8
        for (int j = 0; j < 32; j++) {
            const float4 a  = a4[j];
            const float4 b  = b4[j];
            const float4 vr = v4r[j];
            const float4 vi = v4i[j];
            rr = fmaf(a.x, vr.x, rr); rr = fmaf(a.y, vr.y, rr);
            rr = fmaf(a.z, vr.z, rr); rr = fmaf(a.w, vr.w, rr);
            ri = fmaf(a.x, vi.x, ri); ri = fmaf(a.y, vi.y, ri);
            ri = fmaf(a.z, vi.z, ri); ri = fmaf(a.w, vi.w, ri);
            ir = fmaf(b.x, vr.x, ir); ir = fmaf(b.y, vr.y, ir);
            ir = fmaf(b.z, vr.z, ir); ir = fmaf(b.w, vr.w, ir);
            ii = fmaf(b.x, vi.x, ii); ii = fmaf(b.y, vi.y, ii);
            ii = fmaf(b.z, vi.z, ii); ii = fmaf(b.w, vi.w, ii);
        }
        // Av_re = Ar.vr - Ai.vi ; Av_im = Ai.vr + Ar.vi
        hsrt[m * 8 + kk] = hdr[row] + (rr - ii);
        hsit[m * 8 + kk] = hdi[row] + (ir + ri);
    }
    __syncthreads();

    // ---- stage B: g_partial[kk, n] += sum_m h[kk,m] * W[m0+m, n] (complex) ----
    const int n = tid & 127;          // output column
    const int g = tid >> 7;           // kk group: g*4 .. g*4+3
    {
        float are[4] = {0.f, 0.f, 0.f, 0.f};
        float aim[4] = {0.f, 0.f, 0.f, 0.f};
        const float* Wb = Wv + (size_t)(1 + m0) * 256;   // W rows m0.., stride 256

#pragma unroll 4
        for (int m = 0; m < MCH; m++) {
            const float wre = __ldg(Wb + m * 256 + n);
            const float wim = __ldg(Wb + m * 256 + 128 + n);
            const float4 hre = *reinterpret_cast<const float4*>(&hsrt[m * 8 + g * 4]);
            const float4 him = *reinterpret_cast<const float4*>(&hsit[m * 8 + g * 4]);

            are[0] = fmaf(hre.x, wre, fmaf(-him.x, wim, are[0]));
            aim[0] = fmaf(hre.x, wim, fmaf( him.x, wre, aim[0]));
            are[1] = fmaf(hre.y, wre, fmaf(-him.y, wim, are[1]));
            aim[1] = fmaf(hre.y, wim, fmaf( him.y, wre, aim[1]));
            are[2] = fmaf(hre.z, wre, fmaf(-him.z, wim, are[2]));
            aim[2] = fmaf(hre.z, wim, fmaf( him.z, wre, aim[2]));
            are[3] = fmaf(hre.w, wre, fmaf(-him.w, wim, are[3]));
            aim[3] = fmaf(hre.w, wim, fmaf( him.w, wre, aim[3]));
        }

#pragma unroll
        for (int j = 0; j < 4; j++) {
            const int kidx = k0 + g * 4 + j;
            d_gp_re[mc * (KU * NU) + kidx * NU + n] = are[j];
            d_gp_im[mc * (KU * NU) + kidx * NU + n] = aim[j];
        }
    }
}

// ---------------------------------------------------------------------------
// k3: per-k reduce partials -> mag -> rowsum -> R[k]; last block sums R and
// writes out. grid 128 x 512 threads (best measured config: 7.1us).
// ---------------------------------------------------------------------------
__global__ __launch_bounds__(512) void k3_rate(float* __restrict__ out)
{
    const int k   = blockIdx.x;
    const int tid = threadIdx.x;
    const int n   = tid & 127;
    const int pg  = tid >> 7;   // 0..3

    float gre = 0.f, gim = 0.f;
#pragma unroll
    for (int p = pg; p < NMC; p += 4) {   // 8 partials per thread
        gre += d_gp_re[p * (KU * NU) + k * NU + n];
        gim += d_gp_im[p * (KU * NU) + k * NU + n];
    }

    __shared__ float sre[512];
    __shared__ float sim[512];
    __shared__ float red[128];
    __shared__ float sig_s;
    __shared__ unsigned int last_s;
    sre[tid] = gre;
    sim[tid] = gim;
    __syncthreads();

    if (pg == 0) {
        gre = (sre[n] + sre[n + 128]) + (sre[n + 256] + sre[n + 384]);
        gim = (sim[n] + sim[n + 128]) + (sim[n + 256] + sim[n + 384]);
        const float mag = sqrtf(gre * gre + gim * gim);
        red[n] = mag;
        if (n == k) sig_s = mag;
    }
    __syncthreads();
#pragma unroll
    for (int s = 64; s > 0; s >>= 1) {
        if (tid < s) red[tid] += red[tid + s];
        __syncthreads();
    }
    if (tid == 0) {
        const float sig = sig_s;
        d_R[k] = sig / (red[0] - sig + N0F);
        __threadfence();
        last_s = atomicAdd(&d_ctr, 1u);
    }
    __syncthreads();

    if (last_s == KU - 1) {
        __threadfence();
        if (tid < 128) red[tid] = d_R[tid];
        __syncthreads();
#pragma unroll
        for (int s = 64; s > 0; s >>= 1) {
            if (tid < s) red[tid] += red[tid + s];
            __syncthreads();
        }
        if (tid == 0) {
            out[0] = -red[0] * 1e6f;
            d_ctr = 0;   // reset for next graph replay
        }
    }
}

// ---------------------------------------------------------------------------
extern "C" void kernel_launch(void* const* d_in, const int* in_sizes, int n_in,
                              void* d_out, int out_size)
{
    const float* Wv  = (const float*)d_in[0];  // (1025, 256)
    const float* Ar  = (const float*)d_in[1];  // (128, 1024, 128)
    const float* Ai  = (const float*)d_in[2];
    const float* hdr = (const float*)d_in[3];  // (128, 1024)
    const float* hdi = (const float*)d_in[4];

    k12_fused<<<dim3(NMC, NKT), 256>>>(Wv, Ar, Ai, hdr, hdi);
    k3_rate<<<KU, 512>>>((float*)d_out);
}

// round 13
// speedup vs baseline: 1.6037x; 1.6037x over previous
#include <cuda_runtime.h>
#include <math.h>

#define KU 128      // users (K)
#define MD 1024     // M
#define NU 128      // N (== KU)
#define KT 8        // k rows per block tile
#define MCH 32      // m rows per block chunk
#define NKT (KU / KT)    // 16
#define NMC (MD / MCH)   // 32
static __device__ __constant__ float N0F = 1e-11f;  // 10^(-80/10)/1000

// Scratch (static __device__ — no allocation)
__device__ float d_gp_re[NMC * KU * NU];   // per-m-chunk partials of g (2 MB)
__device__ float d_gp_im[NMC * KU * NU];
__device__ float d_R[KU];
__device__ unsigned int d_ctr;             // last-block counter for k3

__device__ __forceinline__ float dot4(float4 a, float4 b) {
    return fmaf(a.x, b.x, fmaf(a.y, b.y, fmaf(a.z, b.z, a.w * b.w)));
}

// ---------------------------------------------------------------------------
// k12: stage A with 8-lanes-per-row / 4-rows-per-group:
//   every LDG.128 warp-inst covers 4 rows x 128B lines, fully consumed (no L1
//   reuse dependence), and the reduction is only 3 shfl stages (over 8 lanes).
// stage B contracts the h tile against W[m0:m0+32,:] (L2) -> g partials.
// grid (32 mc, 16 kt) = 512 blocks x 256 threads.
// ---------------------------------------------------------------------------
__global__ __launch_bounds__(256) void k12_fused(
    const float* __restrict__ Wv,
    const float* __restrict__ Ar,
    const float* __restrict__ Ai,
    const float* __restrict__ hdr,
    const float* __restrict__ hdi)
{
    __shared__ float vs[256];         // v_re | v_im
    __shared__ float hsrt[MCH * 8];   // h_re transposed [m][kk]
    __shared__ float hsit[MCH * 8];   // h_im transposed [m][kk]

    const int tid  = threadIdx.x;
    const int lane = tid & 31;
    const int warp = tid >> 5;        // 0..7 == kk
    const int c    = lane & 7;        // position within 8-lane row group
    const int sub  = lane >> 3;       // which of the 4 rows

    const int mc = blockIdx.x;        // 0..31
    const int kt = blockIdx.y;        // 0..15
    const int k0 = kt * KT;
    const int m0 = mc * MCH;

    vs[tid] = Wv[tid];                // 256 floats of v
    __syncthreads();

    // ---- stage A: warp kk=warp, 8 groups of 4 rows; 3-stage shfl reduce ----
    {
        const int kk = warp;
        const size_t rowbase = (size_t)(k0 + kk) * MD + m0;
        const float4* v4r = reinterpret_cast<const float4*>(vs);
        const float4* v4i = reinterpret_cast<const float4*>(vs + 128);

#pragma unroll 2
        for (int it = 0; it < 8; ++it) {
            const int m = it * 4 + sub;
            const size_t row = rowbase + m;
            const float4* a4 = reinterpret_cast<const float4*>(Ar + row * NU);
            const float4* b4 = reinterpret_cast<const float4*>(Ai + row * NU);

            const float4 a0 = a4[c],      a1 = a4[c + 8];
            const float4 a2 = a4[c + 16], a3 = a4[c + 24];
            const float4 b0 = b4[c],      b1 = b4[c + 8];
            const float4 b2 = b4[c + 16], b3 = b4[c + 24];

            const float4 vr0 = v4r[c],      vr1 = v4r[c + 8];
            const float4 vr2 = v4r[c + 16], vr3 = v4r[c + 24];
            const float4 vi0 = v4i[c],      vi1 = v4i[c + 8];
            const float4 vi2 = v4i[c + 16], vi3 = v4i[c + 24];

            float sre = (dot4(a0, vr0) + dot4(a1, vr1)) + (dot4(a2, vr2) + dot4(a3, vr3))
                      - (dot4(b0, vi0) + dot4(b1, vi1)) - (dot4(b2, vi2) + dot4(b3, vi3));
            float sim = (dot4(b0, vr0) + dot4(b1, vr1)) + (dot4(b2, vr2) + dot4(b3, vr3))
                      + (dot4(a0, vi0) + dot4(a1, vi1)) + (dot4(a2, vi2) + dot4(a3, vi3));

#pragma unroll
            for (int off = 4; off; off >>= 1) {
                sre += __shfl_xor_sync(0xffffffffu, sre, off);
                sim += __shfl_xor_sync(0xffffffffu, sim, off);
            }
            if (c == 0) {
                hsrt[m * 8 + kk] = hdr[row] + sre;
                hsit[m * 8 + kk] = hdi[row] + sim;
            }
        }
    }
    __syncthreads();

    // ---- stage B: g_partial[kk, n] += sum_m h[kk,m] * W[m0+m, n] (complex) ----
    const int n = tid & 127;          // output column
    const int g = tid >> 7;           // kk group: g*4 .. g*4+3
    {
        float are[4] = {0.f, 0.f, 0.f, 0.f};
        float aim[4] = {0.f, 0.f, 0.f, 0.f};
        const float* Wb = Wv + (size_t)(1 + m0) * 256;   // W rows m0.., stride 256

#pragma unroll 4
        for (int m = 0; m < MCH; m++) {
            const float wre = __ldg(Wb + m * 256 + n);
            const float wim = __ldg(Wb + m * 256 + 128 + n);
            const float4 hre = *reinterpret_cast<const float4*>(&hsrt[m * 8 + g * 4]);
            const float4 him = *reinterpret_cast<const float4*>(&hsit[m * 8 + g * 4]);

            are[0] = fmaf(hre.x, wre, fmaf(-him.x, wim, are[0]));
            aim[0] = fmaf(hre.x, wim, fmaf( him.x, wre, aim[0]));
            are[1] = fmaf(hre.y, wre, fmaf(-him.y, wim, are[1]));
            aim[1] = fmaf(hre.y, wim, fmaf( him.y, wre, aim[1]));
            are[2] = fmaf(hre.z, wre, fmaf(-him.z, wim, are[2]));
            aim[2] = fmaf(hre.z, wim, fmaf( him.z, wre, aim[2]));
            are[3] = fmaf(hre.w, wre, fmaf(-him.w, wim, are[3]));
            aim[3] = fmaf(hre.w, wim, fmaf( him.w, wre, aim[3]));
        }

#pragma unroll
        for (int j = 0; j < 4; j++) {
            const int kidx = k0 + g * 4 + j;
            d_gp_re[mc * (KU * NU) + kidx * NU + n] = are[j];
            d_gp_im[mc * (KU * NU) + kidx * NU + n] = aim[j];
        }
    }
}

// ---------------------------------------------------------------------------
// k3: per-k reduce partials -> mag -> rowsum -> R[k]; last block sums R and
// writes out. grid 128 x 512 threads (measured best k3 config).
// ---------------------------------------------------------------------------
__global__ __launch_bounds__(512) void k3_rate(float* __restrict__ out)
{
    const int k   = blockIdx.x;
    const int tid = threadIdx.x;
    const int n   = tid & 127;
    const int pg  = tid >> 7;   // 0..3

    float gre = 0.f, gim = 0.f;
#pragma unroll
    for (int p = pg; p < NMC; p += 4) {   // 8 partials per thread
        gre += d_gp_re[p * (KU * NU) + k * NU + n];
        gim += d_gp_im[p * (KU * NU) + k * NU + n];
    }

    __shared__ float sre[512];
    __shared__ float sim[512];
    __shared__ float red[128];
    __shared__ float sig_s;
    __shared__ unsigned int last_s;
    sre[tid] = gre;
    sim[tid] = gim;
    __syncthreads();

    if (pg == 0) {
        gre = (sre[n] + sre[n + 128]) + (sre[n + 256] + sre[n + 384]);
        gim = (sim[n] + sim[n + 128]) + (sim[n + 256] + sim[n + 384]);
        const float mag = sqrtf(gre * gre + gim * gim);
        red[n] = mag;
        if (n == k) sig_s = mag;
    }
    __syncthreads();
#pragma unroll
    for (int s = 64; s > 0; s >>= 1) {
        if (tid < s) red[tid] += red[tid + s];
        __syncthreads();
    }
    if (tid == 0) {
        const float sig = sig_s;
        d_R[k] = sig / (red[0] - sig + N0F);
        __threadfence();
        last_s = atomicAdd(&d_ctr, 1u);
    }
    __syncthreads();

    if (last_s == KU - 1) {
        __threadfence();
        if (tid < 128) red[tid] = d_R[tid];
        __syncthreads();
#pragma unroll
        for (int s = 64; s > 0; s >>= 1) {
            if (tid < s) red[tid] += red[tid + s];
            __syncthreads();
        }
        if (tid == 0) {
            out[0] = -red[0] * 1e6f;
            d_ctr = 0;   // reset for next graph replay
        }
    }
}

// ---------------------------------------------------------------------------
extern "C" void kernel_launch(void* const* d_in, const int* in_sizes, int n_in,
                              void* d_out, int out_size)
{
    const float* Wv  = (const float*)d_in[0];  // (1025, 256)
    const float* Ar  = (const float*)d_in[1];  // (128, 1024, 128)
    const float* Ai  = (const float*)d_in[2];
    const float* hdr = (const float*)d_in[3];  // (128, 1024)
    const float* hdi = (const float*)d_in[4];

    k12_fused<<<dim3(NMC, NKT), 256>>>(Wv, Ar, Ai, hdr, hdi);
    k3_rate<<<KU, 512>>>((float*)d_out);
}

// round 14
// speedup vs baseline: 1.6586x; 1.0342x over previous
#include <cuda_runtime.h>
#include <math.h>

#define KU 128      // users (K)
#define MD 1024     // M
#define NU 128      // N (== KU)
#define KT 8        // k rows per block tile
#define MCH 32      // m rows per block chunk
#define NKT (KU / KT)    // 16
#define NMC (MD / MCH)   // 32
static __device__ __constant__ float N0F = 1e-11f;  // 10^(-80/10)/1000

// Scratch (static __device__ — no allocation)
__device__ float d_gp_re[NMC * KU * NU];   // per-m-chunk partials of g (2 MB)
__device__ float d_gp_im[NMC * KU * NU];
__device__ float d_R[KU];
__device__ unsigned int d_ctr;             // last-block counter for k3

__device__ __forceinline__ float dot4(float4 a, float4 b) {
    return fmaf(a.x, b.x, fmaf(a.y, b.y, fmaf(a.z, b.z, a.w * b.w)));
}

// ---------------------------------------------------------------------------
// k12: stage A = 8-lanes-per-row / 4-rows-per-group with an explicit
// double-buffered pipeline: group i+1's 16 LDG.128 are issued BEFORE group i's
// consume (dots + 3-stage shfl), so each warp keeps loads outstanding through
// the dependent phase. v is hoisted to registers (fixed per lane position).
// stage B contracts the h tile against W[m0:m0+32,:] (L2) -> g partials.
// grid (32 mc, 16 kt) = 512 blocks x 256 threads, 2 blocks/SM.
// ---------------------------------------------------------------------------
__global__ __launch_bounds__(256, 2) void k12_fused(
    const float* __restrict__ Wv,
    const float* __restrict__ Ar,
    const float* __restrict__ Ai,
    const float* __restrict__ hdr,
    const float* __restrict__ hdi)
{
    __shared__ float vs[256];         // v_re | v_im
    __shared__ float hsrt[MCH * 8];   // h_re transposed [m][kk]
    __shared__ float hsit[MCH * 8];   // h_im transposed [m][kk]

    const int tid  = threadIdx.x;
    const int lane = tid & 31;
    const int warp = tid >> 5;        // 0..7 == kk
    const int c    = lane & 7;        // position within 8-lane row group
    const int sub  = lane >> 3;       // which of the 4 rows

    const int mc = blockIdx.x;        // 0..31
    const int kt = blockIdx.y;        // 0..15
    const int k0 = kt * KT;
    const int m0 = mc * MCH;

    vs[tid] = Wv[tid];                // 256 floats of v
    __syncthreads();

    // ---- stage A ----
    {
        const int kk = warp;
        const size_t rowbase = (size_t)(k0 + kk) * MD + m0;
        const float4* v4r = reinterpret_cast<const float4*>(vs);
        const float4* v4i = reinterpret_cast<const float4*>(vs + 128);

        // v hoisted to registers: fixed per lane position c (8 float4)
        const float4 vr0 = v4r[c],      vr1 = v4r[c + 8];
        const float4 vr2 = v4r[c + 16], vr3 = v4r[c + 24];
        const float4 vi0 = v4i[c],      vi1 = v4i[c + 8];
        const float4 vi2 = v4i[c + 16], vi3 = v4i[c + 24];

        // prologue: load group 0
        const float4* a4 = reinterpret_cast<const float4*>(Ar + (rowbase + sub) * NU);
        const float4* b4 = reinterpret_cast<const float4*>(Ai + (rowbase + sub) * NU);
        float4 a0 = a4[c], a1 = a4[c + 8], a2 = a4[c + 16], a3 = a4[c + 24];
        float4 b0 = b4[c], b1 = b4[c + 8], b2 = b4[c + 16], b3 = b4[c + 24];

#pragma unroll
        for (int it = 0; it < 8; ++it) {
            // issue next group's loads BEFORE consuming the current group
            float4 na0, na1, na2, na3, nb0, nb1, nb2, nb3;
            if (it < 7) {
                const int mn = (it + 1) * 4 + sub;
                const float4* an = reinterpret_cast<const float4*>(Ar + (rowbase + mn) * NU);
                const float4* bn = reinterpret_cast<const float4*>(Ai + (rowbase + mn) * NU);
                na0 = an[c]; na1 = an[c + 8]; na2 = an[c + 16]; na3 = an[c + 24];
                nb0 = bn[c]; nb1 = bn[c + 8]; nb2 = bn[c + 16]; nb3 = bn[c + 24];
            }

            // consume current group
            float sre = (dot4(a0, vr0) + dot4(a1, vr1)) + (dot4(a2, vr2) + dot4(a3, vr3))
                      - (dot4(b0, vi0) + dot4(b1, vi1)) - (dot4(b2, vi2) + dot4(b3, vi3));
            float sim = (dot4(b0, vr0) + dot4(b1, vr1)) + (dot4(b2, vr2) + dot4(b3, vr3))
                      + (dot4(a0, vi0) + dot4(a1, vi1)) + (dot4(a2, vi2) + dot4(a3, vi3));

#pragma unroll
            for (int off = 4; off; off >>= 1) {
                sre += __shfl_xor_sync(0xffffffffu, sre, off);
                sim += __shfl_xor_sync(0xffffffffu, sim, off);
            }
            const int m = it * 4 + sub;
            if (c == 0) {
                const size_t row = rowbase + m;
                hsrt[m * 8 + kk] = hdr[row] + sre;
                hsit[m * 8 + kk] = hdi[row] + sim;
            }

            if (it < 7) {
                a0 = na0; a1 = na1; a2 = na2; a3 = na3;
                b0 = nb0; b1 = nb1; b2 = nb2; b3 = nb3;
            }
        }
    }
    __syncthreads();

    // ---- stage B: g_partial[kk, n] += sum_m h[kk,m] * W[m0+m, n] (complex) ----
    const int n = tid & 127;          // output column
    const int g = tid >> 7;           // kk group: g*4 .. g*4+3
    {
        float are[4] = {0.f, 0.f, 0.f, 0.f};
        float aim[4] = {0.f, 0.f, 0.f, 0.f};
        const float* Wb = Wv + (size_t)(1 + m0) * 256;   // W rows m0.., stride 256

#pragma unroll 4
        for (int m = 0; m < MCH; m++) {
            const float wre = __ldg(Wb + m * 256 + n);
            const float wim = __ldg(Wb + m * 256 + 128 + n);
            const float4 hre = *reinterpret_cast<const float4*>(&hsrt[m * 8 + g * 4]);
            const float4 him = *reinterpret_cast<const float4*>(&hsit[m * 8 + g * 4]);

            are[0] = fmaf(hre.x, wre, fmaf(-him.x, wim, are[0]));
            aim[0] = fmaf(hre.x, wim, fmaf( him.x, wre, aim[0]));
            are[1] = fmaf(hre.y, wre, fmaf(-him.y, wim, are[1]));
            aim[1] = fmaf(hre.y, wim, fmaf( him.y, wre, aim[1]));
            are[2] = fmaf(hre.z, wre, fmaf(-him.z, wim, are[2]));
            aim[2] = fmaf(hre.z, wim, fmaf( him.z, wre, aim[2]));
            are[3] = fmaf(hre.w, wre, fmaf(-him.w, wim, are[3]));
            aim[3] = fmaf(hre.w, wim, fmaf( him.w, wre, aim[3]));
        }

#pragma unroll
        for (int j = 0; j < 4; j++) {
            const int kidx = k0 + g * 4 + j;
            d_gp_re[mc * (KU * NU) + kidx * NU + n] = are[j];
            d_gp_im[mc * (KU * NU) + kidx * NU + n] = aim[j];
        }
    }
}

// ---------------------------------------------------------------------------
// k3: per-k reduce partials -> mag -> rowsum -> R[k]; last block sums R and
// writes out. grid 128 x 512 threads (measured best k3 config).
// ---------------------------------------------------------------------------
__global__ __launch_bounds__(512) void k3_rate(float* __restrict__ out)
{
    const int k   = blockIdx.x;
    const int tid = threadIdx.x;
    const int n   = tid & 127;
    const int pg  = tid >> 7;   // 0..3

    float gre = 0.f, gim = 0.f;
#pragma unroll
    for (int p = pg; p < NMC; p += 4) {   // 8 partials per thread
        gre += d_gp_re[p * (KU * NU) + k * NU + n];
        gim += d_gp_im[p * (KU * NU) + k * NU + n];
    }

    __shared__ float sre[512];
    __shared__ float sim[512];
    __shared__ float red[128];
    __shared__ float sig_s;
    __shared__ unsigned int last_s;
    sre[tid] = gre;
    sim[tid] = gim;
    __syncthreads();

    if (pg == 0) {
        gre = (sre[n] + sre[n + 128]) + (sre[n + 256] + sre[n + 384]);
        gim = (sim[n] + sim[n + 128]) + (sim[n + 256] + sim[n + 384]);
        const float mag = sqrtf(gre * gre + gim * gim);
        red[n] = mag;
        if (n == k) sig_s = mag;
    }
    __syncthreads();
#pragma unroll
    for (int s = 64; s > 0; s >>= 1) {
        if (tid < s) red[tid] += red[tid + s];
        __syncthreads();
    }
    if (tid == 0) {
        const float sig = sig_s;
        d_R[k] = sig / (red[0] - sig + N0F);
        __threadfence();
        last_s = atomicAdd(&d_ctr, 1u);
    }
    __syncthreads();

    if (last_s == KU - 1) {
        __threadfence();
        if (tid < 128) red[tid] = d_R[tid];
        __syncthreads();
#pragma unroll
        for (int s = 64; s > 0; s >>= 1) {
            if (tid < s) red[tid] += red[tid + s];
            __syncthreads();
        }
        if (tid == 0) {
            out[0] = -red[0] * 1e6f;
            d_ctr = 0;   // reset for next graph replay
        }
    }
}

// ---------------------------------------------------------------------------
extern "C" void kernel_launch(void* const* d_in, const int* in_sizes, int n_in,
                              void* d_out, int out_size)
{
    const float* Wv  = (const float*)d_in[0];  // (1025, 256)
    const float* Ar  = (const float*)d_in[1];  // (128, 1024, 128)
    const float* Ai  = (const float*)d_in[2];
    const float* hdr = (const float*)d_in[3];  // (128, 1024)
    const float* hdi = (const float*)d_in[4];

    k12_fused<<<dim3(NMC, NKT), 256>>>(Wv, Ar, Ai, hdr, hdi);
    k3_rate<<<KU, 512>>>((float*)d_out);
}